// round 7
// baseline (speedup 1.0000x reference)
#include <cuda_runtime.h>
#include <cstddef>

// Problem constants
constexpr int Bn = 8;
constexpr int S  = 160;
constexpr int D  = 256;
constexpr int RS = Bn * S;           // 1280 rows of x (flattened)
constexpr int P  = S * (S - 1) / 2;  // 12720 pairs

// Scratch (allocation-free __device__ globals):
__device__ float g_xa[RS * D];   // x@Wi + bias
__device__ float g_xb[RS * D];   // x@Wj

// ---------------------------------------------------------------------------
// Packed f32x2 helpers
// ---------------------------------------------------------------------------
__device__ __forceinline__ void ffma2(unsigned long long& d,
                                      unsigned long long a,
                                      unsigned long long b) {
    asm("fma.rn.f32x2 %0, %1, %2, %0;" : "+l"(d) : "l"(a), "l"(b));
}
__device__ __forceinline__ unsigned long long add2(unsigned long long a,
                                                   unsigned long long b) {
    unsigned long long r;
    asm("add.rn.f32x2 %0, %1, %2;" : "=l"(r) : "l"(a), "l"(b));
    return r;
}
union F2U { unsigned long long u; float2 f; };
__device__ __forceinline__ float2 as_f2(unsigned long long v) { F2U t; t.u = v; return t.f; }

// ---------------------------------------------------------------------------
// Kernel 1: dual GEMM, M=1280, N=512 (Wi cols | Wj cols), K=256.
// BM=32, BN=64, BK=16, 128 threads, micro-tile 2 rows x 8 cols.
// x tile stored transposed AND pre-duplicated: xs[k][m] = (x[m][k], x[m][k]).
// -> a-operand: ONE LDS.128 gives two splatted f32x2, no MOVs.
// -> per k-step: 8 FFMA2 + 3 LDS.128. Double-buffered smem.
// ---------------------------------------------------------------------------
constexpr int BM = 32, BN = 64, BK = 16;
constexpr int NT = D / BK;  // 16 k-tiles

__global__ __launch_bounds__(128) void gemm_kernel(
    const float* __restrict__ x,
    const float* __restrict__ W,
    const float* __restrict__ bias)
{
    __shared__ float2 xs[2][BK][BM + 2];              // dup/transposed, 16B-aligned rows
    __shared__ __align__(16) float ws[2][BK][BN + 4]; // W tile

    const int t  = threadIdx.x;
    const int r0 = blockIdx.x * BM;
    const int by = blockIdx.y;
    const bool half = (by >= 4);              // false -> Wi/g_xa, true -> Wj/g_xb
    const int c0 = (by * BN) & (D - 1);       // column within the half
    const int wrowbase = half ? D : 0;

    const float4* x4 = reinterpret_cast<const float4*>(x);
    const float4* W4 = reinterpret_cast<const float4*>(W);

    // compute mapping: rows 2*ty, 2*ty+1 ; cols tx*8..tx*8+7
    const int ty = t >> 3;   // 0..15
    const int tx = t & 7;    // 0..7

    // staging mapping
    const int xrow = t >> 2, xch = t & 3;     // x: row, float4-chunk (4 per row)
    const int wrow = t >> 4, wch = t & 15;    // W: row (0..7 then +8), float4-chunk

    unsigned long long acc[2][4];
    #pragma unroll
    for (int r = 0; r < 2; r++)
        #pragma unroll
        for (int c = 0; c < 4; c++) acc[r][c] = 0ull;

    float4 xv, wv0, wv1;

    // prefetch tile 0
    xv  = x4[(size_t)(r0 + xrow) * 64 + xch];
    wv0 = W4[(size_t)(wrowbase + wrow)     * 64 + (c0 >> 2) + wch];
    wv1 = W4[(size_t)(wrowbase + 8 + wrow) * 64 + (c0 >> 2) + wch];

    // store tile 0
    {
        const int kk = xch * 4;
        xs[0][kk + 0][xrow] = make_float2(xv.x, xv.x);
        xs[0][kk + 1][xrow] = make_float2(xv.y, xv.y);
        xs[0][kk + 2][xrow] = make_float2(xv.z, xv.z);
        xs[0][kk + 3][xrow] = make_float2(xv.w, xv.w);
        *reinterpret_cast<float4*>(&ws[0][wrow][wch * 4])     = wv0;
        *reinterpret_cast<float4*>(&ws[0][8 + wrow][wch * 4]) = wv1;
    }
    __syncthreads();

    #pragma unroll 1
    for (int kt = 0; kt < NT; kt++) {
        const int cur = kt & 1;
        const int nxt = cur ^ 1;

        if (kt + 1 < NT) {  // global prefetch into registers
            xv  = x4[(size_t)(r0 + xrow) * 64 + (kt + 1) * 4 + xch];
            wv0 = W4[(size_t)(wrowbase + (kt + 1) * BK + wrow)     * 64 + (c0 >> 2) + wch];
            wv1 = W4[(size_t)(wrowbase + (kt + 1) * BK + 8 + wrow) * 64 + (c0 >> 2) + wch];
        }

        #pragma unroll
        for (int k = 0; k < BK; k++) {
            // one LDS.128: two pre-splatted a-operands (rows 2ty, 2ty+1)
            const ulonglong2 ad = *reinterpret_cast<const ulonglong2*>(&xs[cur][k][2 * ty]);
            // two LDS.128: eight W columns as four f32x2 pairs
            const ulonglong2 wq0 = *reinterpret_cast<const ulonglong2*>(&ws[cur][k][tx * 8]);
            const ulonglong2 wq1 = *reinterpret_cast<const ulonglong2*>(&ws[cur][k][tx * 8 + 4]);
            ffma2(acc[0][0], ad.x, wq0.x); ffma2(acc[0][1], ad.x, wq0.y);
            ffma2(acc[0][2], ad.x, wq1.x); ffma2(acc[0][3], ad.x, wq1.y);
            ffma2(acc[1][0], ad.y, wq0.x); ffma2(acc[1][1], ad.y, wq0.y);
            ffma2(acc[1][2], ad.y, wq1.x); ffma2(acc[1][3], ad.y, wq1.y);
        }

        if (kt + 1 < NT) {
            const int kk = xch * 4;
            xs[nxt][kk + 0][xrow] = make_float2(xv.x, xv.x);
            xs[nxt][kk + 1][xrow] = make_float2(xv.y, xv.y);
            xs[nxt][kk + 2][xrow] = make_float2(xv.z, xv.z);
            xs[nxt][kk + 3][xrow] = make_float2(xv.w, xv.w);
            *reinterpret_cast<float4*>(&ws[nxt][wrow][wch * 4])     = wv0;
            *reinterpret_cast<float4*>(&ws[nxt][8 + wrow][wch * 4]) = wv1;
            __syncthreads();
        }
    }

    // epilogue: bias on the Wi half, write g_xa / g_xb
    const int cc = c0 + tx * 8;
    float bv[8];
    #pragma unroll
    for (int c = 0; c < 8; c++) bv[c] = 0.0f;
    if (!half) {
        const float4 b0 = *reinterpret_cast<const float4*>(&bias[cc]);
        const float4 b1 = *reinterpret_cast<const float4*>(&bias[cc + 4]);
        bv[0] = b0.x; bv[1] = b0.y; bv[2] = b0.z; bv[3] = b0.w;
        bv[4] = b1.x; bv[5] = b1.y; bv[6] = b1.z; bv[7] = b1.w;
    }
    float* dst = half ? g_xb : g_xa;
    #pragma unroll
    for (int r = 0; r < 2; r++) {
        const int row = r0 + 2 * ty + r;
        float o[8];
        #pragma unroll
        for (int c = 0; c < 4; c++) {
            const float2 f = as_f2(acc[r][c]);
            o[2 * c]     = f.x + bv[2 * c];
            o[2 * c + 1] = f.y + bv[2 * c + 1];
        }
        *reinterpret_cast<float4*>(&dst[(size_t)row * D + cc]) =
            make_float4(o[0], o[1], o[2], o[3]);
        *reinterpret_cast<float4*>(&dst[(size_t)row * D + cc + 4]) =
            make_float4(o[4], o[5], o[6], o[7]);
    }
}

// ---------------------------------------------------------------------------
// Kernel 2: pairwise expansion. Grid (55 triangle tiles, Bn, 2 D-halves),
// block 256 = 8 warps. Each warp owns TWO xa rows in REGISTERS (i = 2w, 2w+1);
// only xb staged in smem. Per j-step: 1 LDS.128 -> 2 STG.128 (amortized
// MIO: ~14 cyc per 512B store vs 20 before). Packed f32x2 adds.
// ---------------------------------------------------------------------------
constexpr int TI  = 16;
constexpr int TPD = S / TI;                      // 10
constexpr int NTILES = TPD * (TPD + 1) / 2;      // 55

__global__ __launch_bounds__(256) void expand_kernel(float* __restrict__ out)
{
    __shared__ float4 sb[TI][32];

    // linear tile index -> (ti, tj) upper triangle incl. diagonal
    int rem = blockIdx.x, ti = 0;
    while (rem >= TPD - ti) { rem -= TPD - ti; ti++; }
    const int tj = ti + rem;

    const int b   = blockIdx.y;
    const int h   = blockIdx.z;   // D half
    const int i0  = ti * TI;
    const int j0  = tj * TI;
    const int tid = threadIdx.x;
    const int warp = tid >> 5;
    const int lane = tid & 31;

    const float4* xa4 = reinterpret_cast<const float4*>(g_xa);
    const float4* xb4 = reinterpret_cast<const float4*>(g_xb);

    // stage 16 xb half-rows
    #pragma unroll
    for (int q = 0; q < 2; q++) {
        const int k = tid + q * 256;
        const int r = k >> 5, c = k & 31;
        sb[r][c] = xb4[(size_t)(b * S + j0 + r) * 64 + h * 32 + c];
    }

    // this warp's two xa rows -> registers (as packed f32x2 pairs)
    const int ia = i0 + 2 * warp;
    const int ib = ia + 1;
    const ulonglong2 a0 = reinterpret_cast<const ulonglong2*>(xa4)[(size_t)(b * S + ia) * 32 + h * 16 + (lane >> 1) * 2 + (lane & 1)];
    // simpler: reload as float4 (same data path)
    const float4 A0 = xa4[(size_t)(b * S + ia) * 64 + h * 32 + lane];
    const float4 A1 = xa4[(size_t)(b * S + ib) * 64 + h * 32 + lane];
    (void)a0;
    F2U a0lo, a0hi, a1lo, a1hi;
    a0lo.f = make_float2(A0.x, A0.y); a0hi.f = make_float2(A0.z, A0.w);
    a1lo.f = make_float2(A1.x, A1.y); a1hi.f = make_float2(A1.z, A1.w);

    __syncthreads();

    // p(i,j) = i*(2S-1-i)/2 + j - i - 1
    const int pb0 = ((2 * S - 1 - ia) * ia) / 2 + j0 - ia - 1;
    const int pb1 = ((2 * S - 1 - ib) * ib) / 2 + j0 - ib - 1;

    float4* out4 = reinterpret_cast<float4*>(out);
    float4* o0 = out4 + ((size_t)b * P + pb0) * 64 + h * 32 + lane;
    float4* o1 = out4 + ((size_t)b * P + pb1) * 64 + h * 32 + lane;

    #pragma unroll
    for (int jj = 0; jj < TI; jj++) {
        const float4 v = sb[jj][lane];
        F2U vlo, vhi; vlo.f = make_float2(v.x, v.y); vhi.f = make_float2(v.z, v.w);
        const int j = j0 + jj;

        if (j > ia) {
            F2U rlo, rhi;
            rlo.u = add2(a0lo.u, vlo.u);
            rhi.u = add2(a0hi.u, vhi.u);
            o0[(size_t)jj * 64] = make_float4(rlo.f.x, rlo.f.y, rhi.f.x, rhi.f.y);
        }
        if (j > ib) {
            F2U rlo, rhi;
            rlo.u = add2(a1lo.u, vlo.u);
            rhi.u = add2(a1hi.u, vhi.u);
            o1[(size_t)jj * 64] = make_float4(rlo.f.x, rlo.f.y, rhi.f.x, rhi.f.y);
        }
    }
}

// ---------------------------------------------------------------------------
extern "C" void kernel_launch(void* const* d_in, const int* in_sizes, int n_in,
                              void* d_out, int out_size)
{
    const float* x    = (const float*)d_in[0];   // (8,160,256) f32
    const float* W    = (const float*)d_in[1];   // (512,256)   f32
    const float* bias = (const float*)d_in[2];   // (256,)      f32
    float* out = (float*)d_out;                  // (8,12720,256) f32

    gemm_kernel<<<dim3(RS / BM, 2 * D / BN), 128>>>(x, W, bias);
    expand_kernel<<<dim3(NTILES, Bn, 2), 256>>>(out);
}